// round 3
// baseline (speedup 1.0000x reference)
#include <cuda_runtime.h>

// Shapes (fixed by the reference setup_inputs):
//   predicted_noise [32, 4, 512, 512] f32   (d_in[0])
//   target_noise    [32, 4, 512, 512] f32   (d_in[1])
//   text_tokens     [32, 64] int64          (d_in[2], UNUSED by the math)
//   text_positions  [32, 64, 2] f32         (d_in[3])
// Output: 1 x f32 scalar.
//
// With WEIGHT = 1.0 the result is exactly:
//   mean over (b,c,h,w) of (1 + 3*mask[b,h,w]) * (p - t)^2
// where mask is the union of 10x10 boxes around valid tokens.

#define NB 32
#define NC 4
#define NH 512
#define NW 512
#define NT 64
#define BOX 5

#define WORDS_PER_ROW   (NW / 32)                 // 16
#define WORDS_PER_BATCH (NH * WORDS_PER_ROW)      // 8192 = 2^13
#define MASK_WORDS      (NB * WORDS_PER_BATCH)    // 262144 (1 MB)
#define N_ELEMS         (NB * NC * NH * NW)       // 33554432 = 2^25
#define N4              (N_ELEMS / 4)             // 8388608

// Device-global scratch (allocation-free per harness rules).
__device__ unsigned g_mask[MASK_WORDS];
__device__ double   g_acc;

// ---------------------------------------------------------------------------
// Kernel 1: zero the mask bitfield and the accumulator (graph replays reuse
// the globals, so this must run every launch).
// ---------------------------------------------------------------------------
__global__ void zero_kernel() {
    int i = blockIdx.x * blockDim.x + threadIdx.x;
    if (i < MASK_WORDS) g_mask[i] = 0u;
    if (i == 0) g_acc = 0.0;
}

// ---------------------------------------------------------------------------
// Kernel 2: paint token boxes into the bitfield.
// One thread per (batch, token): <=10 rows x <=2 atomicOr each (~40K atomics).
// ---------------------------------------------------------------------------
__global__ void paint_kernel(const float* __restrict__ pos) {
    int b = blockIdx.x;   // 0..31
    int t = threadIdx.x;  // 0..63
    float x = pos[(b * NT + t) * 2 + 0];
    float y = pos[(b * NT + t) * 2 + 1];
    if (!(x > 0.0f && y > 0.0f)) return;

    int xp = (int)floorf(x * (float)NW);
    int yp = (int)floorf(y * (float)NH);
    int x0 = max(xp - BOX, 0);
    int x1 = min(xp + BOX, NW);
    int y0 = max(yp - BOX, 0);
    int y1 = min(yp + BOX, NH);
    if (x0 >= x1 || y0 >= y1) return;

    int w0 = x0 >> 5;
    int w1 = (x1 - 1) >> 5;
    unsigned m0, m1 = 0u;
    if (w0 == w1) {
        // width <= 10 < 32, so the shift below never hits 32
        m0 = ((1u << (x1 - x0)) - 1u) << (x0 & 31);
    } else {
        m0 = ~0u << (x0 & 31);
        // bits in the second word: x1 - w1*32 is in [1, 9] here (width <= 10)
        m1 = (1u << (x1 - (w1 << 5))) - 1u;
    }

    unsigned base = (unsigned)b * WORDS_PER_BATCH;
    for (int i = y0; i < y1; i++) {
        unsigned row = base + (unsigned)i * WORDS_PER_ROW;
        atomicOr(&g_mask[row + w0], m0);
        if (w0 != w1) atomicOr(&g_mask[row + w1], m1);
    }
}

// ---------------------------------------------------------------------------
// Kernel 3: streaming weighted-SSE reduce. float4 per iteration; the 4 mask
// bits of a 4-aligned column group always sit inside one uint32 (4 | 32).
// All index math is shifts since every dim is a power of two:
//   float index fi: batch = fi >> 20, spatial = fi & (2^18 - 1).
// ---------------------------------------------------------------------------
__global__ void reduce_kernel(const float4* __restrict__ p,
                              const float4* __restrict__ q) {
    float sum = 0.0f;
    int stride = gridDim.x * blockDim.x;
    #pragma unroll 4
    for (int i = blockIdx.x * blockDim.x + threadIdx.x; i < N4; i += stride) {
        float4 a = p[i];
        float4 b = q[i];
        unsigned fi = (unsigned)i << 2;
        unsigned bidx = fi >> 20;                 // / (C*H*W) = 2^20
        unsigned spatial = fi & ((1u << 18) - 1u);// % (H*W)   = 2^18
        unsigned word = g_mask[(bidx << 13) + (spatial >> 5)];
        unsigned bits = word >> (spatial & 31u);

        float d0 = a.x - b.x; d0 *= d0;
        float d1 = a.y - b.y; d1 *= d1;
        float d2 = a.z - b.z; d2 *= d2;
        float d3 = a.w - b.w; d3 *= d3;

        float m = (float)(bits & 1u)         * d0
                + (float)((bits >> 1) & 1u)  * d1
                + (float)((bits >> 2) & 1u)  * d2
                + (float)((bits >> 3) & 1u)  * d3;
        sum += (d0 + d1 + d2 + d3) + 3.0f * m;
    }

    // warp reduce
    #pragma unroll
    for (int o = 16; o > 0; o >>= 1)
        sum += __shfl_xor_sync(0xFFFFFFFFu, sum, o);

    __shared__ float ssum[32];
    int lane = threadIdx.x & 31;
    int wid  = threadIdx.x >> 5;
    if (lane == 0) ssum[wid] = sum;
    __syncthreads();
    if (wid == 0) {
        float v = (lane < (int)(blockDim.x >> 5)) ? ssum[lane] : 0.0f;
        #pragma unroll
        for (int o = 16; o > 0; o >>= 1)
            v += __shfl_xor_sync(0xFFFFFFFFu, v, o);
        if (lane == 0) atomicAdd(&g_acc, (double)v);
    }
}

// ---------------------------------------------------------------------------
// Kernel 4: divide by N and write the scalar output.
// ---------------------------------------------------------------------------
__global__ void finalize_kernel(float* __restrict__ out) {
    out[0] = (float)(g_acc * (1.0 / (double)N_ELEMS));
}

extern "C" void kernel_launch(void* const* d_in, const int* in_sizes, int n_in,
                              void* d_out, int out_size) {
    const float* pred = (const float*)d_in[0];
    const float* targ = (const float*)d_in[1];
    // d_in[2] (text_tokens) is unused by the math.
    const float* pos  = (const float*)d_in[3];
    float* out = (float*)d_out;

    zero_kernel<<<(MASK_WORDS + 255) / 256, 256>>>();
    paint_kernel<<<NB, NT>>>(pos);
    reduce_kernel<<<2048, 256>>>((const float4*)pred, (const float4*)targ);
    finalize_kernel<<<1, 1>>>(out);
}

// round 4
// speedup vs baseline: 1.0484x; 1.0484x over previous
#include <cuda_runtime.h>

// Shapes (fixed by the reference setup_inputs):
//   predicted_noise [32, 4, 512, 512] f32   (d_in[0])
//   target_noise    [32, 4, 512, 512] f32   (d_in[1])
//   text_tokens     [32, 64] int64          (d_in[2], UNUSED by the math)
//   text_positions  [32, 64, 2] f32         (d_in[3])
// Output: 1 x f32 scalar.
//
// With WEIGHT = 1.0 the result collapses to:
//   mean over (b,c,h,w) of (1 + 3*mask[b,h,w]) * (p - t)^2
// where mask is the union of 10x10 boxes around valid tokens.
//
// Single-kernel design: each block owns (batch, 16-row chunk) across all 4
// channels, rebuilds the 16-row mask slice in SMEM from the 64 tokens
// (no global mask, no zero/paint kernels), streams its 256 KB, and the
// last block (threadfence + wrapping atomicInc) folds the 1024 partials
// and writes the scalar. One launch total.

#define NB 32
#define NC 4
#define NH 512
#define NW 512
#define NT 64
#define BOX 5

#define ROWS_PER_BLOCK 16
#define CHUNKS_PER_BATCH (NH / ROWS_PER_BLOCK)     // 32
#define GRID (NB * CHUNKS_PER_BATCH)               // 1024
#define THREADS 256
#define N_ELEMS (NB * NC * NH * NW)                // 33554432
// float4 counts
#define F4_PER_ROW (NW / 4)                        // 128
#define F4_PER_IMG (NH * NW / 4)                   // 65536 = 2^16
#define F4_PER_BLOCK (NC * ROWS_PER_BLOCK * F4_PER_ROW)  // 8192
#define ITERS (F4_PER_BLOCK / THREADS)             // 32

__device__ float    g_partials[GRID];
__device__ unsigned g_count = 0;   // wraps back to 0 via atomicInc each replay

__global__ void __launch_bounds__(THREADS)
fused_loss_kernel(const float4* __restrict__ p,
                  const float4* __restrict__ q,
                  const float*  __restrict__ pos,
                  float* __restrict__ out) {
    __shared__ unsigned smask[ROWS_PER_BLOCK][NW / 32];   // 16 x 16 words = 1 KB
    __shared__ float    ssum[THREADS / 32];
    __shared__ bool     s_last;

    const int tid   = threadIdx.x;
    const int batch = blockIdx.x >> 5;          // / CHUNKS_PER_BATCH
    const int chunk = blockIdx.x & 31;
    const int h0    = chunk * ROWS_PER_BLOCK;

    // ---- build mask slice for rows [h0, h0+16) in SMEM ----
    {
        // zero the 256 smem words (one per thread)
        if (tid < ROWS_PER_BLOCK * (NW / 32))
            ((unsigned*)smask)[tid] = 0u;
        __syncthreads();

        if (tid < NT) {
            float x = pos[(batch * NT + tid) * 2 + 0];
            float y = pos[(batch * NT + tid) * 2 + 1];
            if (x > 0.0f && y > 0.0f) {
                int xp = (int)floorf(x * (float)NW);
                int yp = (int)floorf(y * (float)NH);
                int x0 = max(xp - BOX, 0);
                int x1 = min(xp + BOX, NW);
                int y0 = max(max(yp - BOX, 0), h0);
                int y1 = min(min(yp + BOX, NH), h0 + ROWS_PER_BLOCK);
                if (x0 < x1 && y0 < y1) {
                    int w0 = x0 >> 5;
                    int w1 = (x1 - 1) >> 5;
                    unsigned m0, m1 = 0u;
                    if (w0 == w1) {
                        m0 = ((1u << (x1 - x0)) - 1u) << (x0 & 31);  // width <= 10 < 32
                    } else {
                        m0 = ~0u << (x0 & 31);
                        m1 = (1u << (x1 - (w1 << 5))) - 1u;          // 1..9 bits
                    }
                    for (int i = y0; i < y1; i++) {
                        atomicOr(&smask[i - h0][w0], m0);
                        if (w0 != w1) atomicOr(&smask[i - h0][w1], m1);
                    }
                }
            }
        }
        __syncthreads();
    }

    // ---- stream this block's 256 KB (4 channels x 16 rows x 512 cols x 2) ----
    const int base_img = batch * NC;   // image index of channel 0
    float sum = 0.0f;
    #pragma unroll 4
    for (int k = 0; k < ITERS; k++) {
        int idx = tid + k * THREADS;          // 0..8191
        int ch  = idx >> 11;                  // / (16*128)
        int rem = idx & 2047;
        int row = rem >> 7;                   // 0..15
        int c4  = rem & 127;                  // float4 column
        int g = ((base_img + ch) << 16) + ((h0 + row) << 7) + c4;

        float4 a = p[g];
        float4 b = q[g];
        unsigned bits = smask[row][c4 >> 3] >> ((c4 & 7) << 2);

        float d0 = a.x - b.x; d0 *= d0;
        float d1 = a.y - b.y; d1 *= d1;
        float d2 = a.z - b.z; d2 *= d2;
        float d3 = a.w - b.w; d3 *= d3;

        float m = (float)(bits & 1u)        * d0
                + (float)((bits >> 1) & 1u) * d1
                + (float)((bits >> 2) & 1u) * d2
                + (float)((bits >> 3) & 1u) * d3;
        sum += (d0 + d1 + d2 + d3) + 3.0f * m;
    }

    // ---- block reduce ----
    #pragma unroll
    for (int o = 16; o > 0; o >>= 1)
        sum += __shfl_xor_sync(0xFFFFFFFFu, sum, o);
    int lane = tid & 31, wid = tid >> 5;
    if (lane == 0) ssum[wid] = sum;
    __syncthreads();
    if (wid == 0) {
        float v = (lane < THREADS / 32) ? ssum[lane] : 0.0f;
        #pragma unroll
        for (int o = 4; o > 0; o >>= 1)
            v += __shfl_xor_sync(0xFFFFFFFFu, v, o);
        if (lane == 0) {
            g_partials[blockIdx.x] = v;
            __threadfence();
            unsigned prev = atomicInc(&g_count, GRID - 1);  // wraps to 0 after last
            s_last = (prev == GRID - 1);
        }
    }
    __syncthreads();

    // ---- last block folds all partials and writes the scalar ----
    if (s_last) {
        double d = 0.0;
        for (int i = tid; i < GRID; i += THREADS)
            d += (double)g_partials[i];
        #pragma unroll
        for (int o = 16; o > 0; o >>= 1)
            d += __shfl_xor_sync(0xFFFFFFFFu, d, o);
        __shared__ double dsum[THREADS / 32];
        if (lane == 0) dsum[wid] = d;
        __syncthreads();
        if (wid == 0) {
            double t = (lane < THREADS / 32) ? dsum[lane] : 0.0;
            #pragma unroll
            for (int o = 4; o > 0; o >>= 1)
                t += __shfl_xor_sync(0xFFFFFFFFu, t, o);
            if (lane == 0)
                out[0] = (float)(t * (1.0 / (double)N_ELEMS));
        }
    }
}

extern "C" void kernel_launch(void* const* d_in, const int* in_sizes, int n_in,
                              void* d_out, int out_size) {
    const float* pred = (const float*)d_in[0];
    const float* targ = (const float*)d_in[1];
    // d_in[2] (text_tokens) is unused by the math.
    const float* pos  = (const float*)d_in[3];
    fused_loss_kernel<<<GRID, THREADS>>>((const float4*)pred,
                                         (const float4*)targ,
                                         pos, (float*)d_out);
}